// round 1
// baseline (speedup 1.0000x reference)
#include <cuda_runtime.h>
#include <cuda_bf16.h>

// Problem constants: B=2, T=2048, D=1024, H=16, HD=64
#define BB 2
#define TT 2048
#define DD 1024
#define HH 16
#define HD 64
#define BT (BB * TT)  // 4096 rows for the projection GEMMs

// Scratch (allocation-free rule: __device__ globals). 16 MB each.
__device__ float g_q[BB * TT * DD];
__device__ float g_k[BB * TT * DD];
__device__ float g_v[BB * TT * DD];
__device__ float g_y[BB * TT * DD];

// ---------------------------------------------------------------------------
// GEMM (NT): C[m,n] = sum_k A[m,k] * W[n,k] + bias[n]
// A: [M,K] row-major, W: [N,K] row-major (PyTorch-style x @ W.T + b)
// 64x64 tile, BK=16, 256 threads, 4x4 microtile per thread.
// ---------------------------------------------------------------------------
__global__ __launch_bounds__(256) void gemm_nt_bias(
    const float* __restrict__ A, const float* __restrict__ W,
    const float* __restrict__ bias, float* __restrict__ C,
    int M, int N, int K)
{
    const int BM = 64, BN = 64, BK = 16;
    __shared__ float As[64][17];  // pad 17: conflict-free column reads
    __shared__ float Ws[64][17];

    int tid = threadIdx.x;
    int tx = tid & 15;       // 0..15 -> N microtile
    int ty = tid >> 4;       // 0..15 -> M microtile
    int bm = blockIdx.y * BM;
    int bn = blockIdx.x * BN;

    // float4 cooperative load mapping: 64 rows x 4 float4 per tile = 256 loads
    int lr = tid >> 2;            // 0..63 (row in tile)
    int lc = (tid & 3) * 4;       // 0,4,8,12 (col in tile)

    float acc[4][4];
#pragma unroll
    for (int i = 0; i < 4; i++)
#pragma unroll
        for (int j = 0; j < 4; j++) acc[i][j] = 0.f;

    for (int k0 = 0; k0 < K; k0 += BK) {
        float4 av = *(const float4*)&A[(size_t)(bm + lr) * K + k0 + lc];
        float4 wv = *(const float4*)&W[(size_t)(bn + lr) * K + k0 + lc];
        As[lr][lc + 0] = av.x; As[lr][lc + 1] = av.y;
        As[lr][lc + 2] = av.z; As[lr][lc + 3] = av.w;
        Ws[lr][lc + 0] = wv.x; Ws[lr][lc + 1] = wv.y;
        Ws[lr][lc + 2] = wv.z; Ws[lr][lc + 3] = wv.w;
        __syncthreads();

#pragma unroll
        for (int kk = 0; kk < BK; kk++) {
            float a[4], b[4];
#pragma unroll
            for (int i = 0; i < 4; i++) a[i] = As[ty * 4 + i][kk];
#pragma unroll
            for (int j = 0; j < 4; j++) b[j] = Ws[tx * 4 + j][kk];
#pragma unroll
            for (int i = 0; i < 4; i++)
#pragma unroll
                for (int j = 0; j < 4; j++)
                    acc[i][j] = fmaf(a[i], b[j], acc[i][j]);
        }
        __syncthreads();
    }

#pragma unroll
    for (int i = 0; i < 4; i++) {
        int m = bm + ty * 4 + i;
#pragma unroll
        for (int j = 0; j < 4; j++) {
            int n = bn + tx * 4 + j;
            C[(size_t)m * N + n] = acc[i][j] + bias[n];
        }
    }
}

// ---------------------------------------------------------------------------
// Causal flash attention, fp32.
// Layout of Q/K/V: [B, T, H*HD] (head h lives at columns h*HD .. h*HD+63).
// Block = 64 threads; thread t owns query row (blockIdx.x*64 + t).
// q and o accumulators in registers; K/V 64x64 tiles staged in smem.
// Key tile processed in 4 chunks of 16 so the score vector stays in regs.
// ---------------------------------------------------------------------------
__global__ __launch_bounds__(64) void attn_causal(
    const float* __restrict__ Q, const float* __restrict__ Kg,
    const float* __restrict__ Vg, float* __restrict__ Y)
{
    __shared__ __align__(16) float Ks[64][68];  // 68: float4-aligned rows, odd*4 stride
    __shared__ __align__(16) float Vs[64][68];

    int qb  = blockIdx.x;          // query tile index (0..31)
    int bh  = blockIdx.y;          // b*H + h        (0..31)
    int b   = bh >> 4;
    int h   = bh & 15;
    int tid = threadIdx.x;         // 0..63
    int qrow = qb * 64 + tid;

    const float scale = 0.125f;    // 1/sqrt(64)

    float q[HD];
    const float* qp = Q + ((size_t)b * TT + qrow) * DD + h * HD;
#pragma unroll
    for (int d = 0; d < HD; d++) q[d] = qp[d] * scale;

    float o[HD];
#pragma unroll
    for (int d = 0; d < HD; d++) o[d] = 0.f;
    float m = -1e30f, l = 0.f;

    for (int kb = 0; kb <= qb; kb++) {
        const float* kp = Kg + ((size_t)b * TT + kb * 64) * DD + h * HD;
        const float* vp = Vg + ((size_t)b * TT + kb * 64) * DD + h * HD;
        // cooperative tile load: thread t loads column t of every row (coalesced)
        for (int r = 0; r < 64; r++) {
            Ks[r][tid] = kp[(size_t)r * DD + tid];
            Vs[r][tid] = vp[(size_t)r * DD + tid];
        }
        __syncthreads();

        int kbase = kb * 64;
#pragma unroll 1
        for (int c = 0; c < 4; c++) {
            float s[16];
#pragma unroll
            for (int jj = 0; jj < 16; jj++) {
                int j = c * 16 + jj;
                float acc = 0.f;
#pragma unroll
                for (int d4 = 0; d4 < HD / 4; d4++) {
                    float4 k4 = *(const float4*)&Ks[j][d4 * 4];
                    acc = fmaf(q[d4 * 4 + 0], k4.x, acc);
                    acc = fmaf(q[d4 * 4 + 1], k4.y, acc);
                    acc = fmaf(q[d4 * 4 + 2], k4.z, acc);
                    acc = fmaf(q[d4 * 4 + 3], k4.w, acc);
                }
                // causal mask: chunk 0 always has >=1 unmasked (j=0 -> kbase <= qrow),
                // so m is finite before any fully-masked chunk -> exp(-1e30 - m) == 0.
                s[jj] = (kbase + j <= qrow) ? acc : -1e30f;
            }
            float mnew = m;
#pragma unroll
            for (int jj = 0; jj < 16; jj++) mnew = fmaxf(mnew, s[jj]);
            float alpha = __expf(m - mnew);
            l *= alpha;
#pragma unroll
            for (int d = 0; d < HD; d++) o[d] *= alpha;
#pragma unroll
            for (int jj = 0; jj < 16; jj++) {
                int j = c * 16 + jj;
                float p = __expf(s[jj] - mnew);
                l += p;
#pragma unroll
                for (int d4 = 0; d4 < HD / 4; d4++) {
                    float4 v4 = *(const float4*)&Vs[j][d4 * 4];
                    o[d4 * 4 + 0] = fmaf(p, v4.x, o[d4 * 4 + 0]);
                    o[d4 * 4 + 1] = fmaf(p, v4.y, o[d4 * 4 + 1]);
                    o[d4 * 4 + 2] = fmaf(p, v4.z, o[d4 * 4 + 2]);
                    o[d4 * 4 + 3] = fmaf(p, v4.w, o[d4 * 4 + 3]);
                }
            }
            m = mnew;
        }
        __syncthreads();
    }

    float inv = 1.f / l;
    float* yp = Y + ((size_t)b * TT + qrow) * DD + h * HD;
#pragma unroll
    for (int d = 0; d < HD; d++) yp[d] = o[d] * inv;
}

// ---------------------------------------------------------------------------
// Launch: Q/K/V projections -> flash attention -> output projection.
// All plain kernel launches on the capture stream; no allocs, no syncs.
// ---------------------------------------------------------------------------
extern "C" void kernel_launch(void* const* d_in, const int* in_sizes, int n_in,
                              void* d_out, int out_size)
{
    const float* x  = (const float*)d_in[0];
    const float* Wq = (const float*)d_in[1];
    const float* bq = (const float*)d_in[2];
    const float* Wk = (const float*)d_in[3];
    const float* bk = (const float*)d_in[4];
    const float* Wv = (const float*)d_in[5];
    const float* bv = (const float*)d_in[6];
    const float* Wp = (const float*)d_in[7];
    const float* bp = (const float*)d_in[8];
    float* out = (float*)d_out;

    float *qg, *kg, *vg, *yg;
    cudaGetSymbolAddress((void**)&qg, g_q);
    cudaGetSymbolAddress((void**)&kg, g_k);
    cudaGetSymbolAddress((void**)&vg, g_v);
    cudaGetSymbolAddress((void**)&yg, g_y);

    dim3 gb(DD / 64, BT / 64);   // (16, 64)
    gemm_nt_bias<<<gb, 256>>>(x, Wq, bq, qg, BT, DD, DD);
    gemm_nt_bias<<<gb, 256>>>(x, Wk, bk, kg, BT, DD, DD);
    gemm_nt_bias<<<gb, 256>>>(x, Wv, bv, vg, BT, DD, DD);

    dim3 ga(TT / 64, BB * HH);   // (32, 32)
    attn_causal<<<ga, 64>>>(qg, kg, vg, yg);

    gemm_nt_bias<<<gb, 256>>>(yg, Wp, bp, out, BT, DD, DD);
}

// round 4
// speedup vs baseline: 1.2843x; 1.2843x over previous
#include <cuda_runtime.h>
#include <cuda_bf16.h>
#include <cstdint>

// Problem constants: B=2, T=2048, D=1024, H=16, HD=64
#define BB 2
#define TT 2048
#define DD 1024
#define HH 16
#define HD 64
#define BT (BB * TT)  // 4096 rows for projection GEMMs

// ---------------------------------------------------------------------------
// Scratch (__device__ globals; no allocs allowed)
// ---------------------------------------------------------------------------
__device__ float g_q[BB * TT * DD];
__device__ float g_k[BB * TT * DD];
__device__ float g_v[BB * TT * DD];
__device__ float g_y[BB * TT * DD];
__device__ __nv_bfloat16 g_xh[BT * DD];      // split of x (reused for y)
__device__ __nv_bfloat16 g_xl[BT * DD];
__device__ __nv_bfloat16 g_wh[4 * DD * DD];  // splits of Wq,Wk,Wv,Wp
__device__ __nv_bfloat16 g_wl[4 * DD * DD];

// ---------------------------------------------------------------------------
// PTX helpers: base-target tensor core path (no 'a'-target features).
// mma.sync + ldmatrix + cp.async are all valid on compute_103 base.
// ---------------------------------------------------------------------------
__device__ __forceinline__ uint32_t smem_u32(const void* p) {
    uint32_t a;
    asm("{ .reg .u64 t; cvta.to.shared.u64 t, %1; cvt.u32.u64 %0, t; }"
        : "=r"(a) : "l"(p));
    return a;
}

#define CP_ASYNC16(dst_u32, src_ptr) \
    asm volatile("cp.async.cg.shared.global [%0], [%1], 16;" \
                 :: "r"(dst_u32), "l"(src_ptr))
#define CP_COMMIT() asm volatile("cp.async.commit_group;" ::: "memory")
#define CP_WAIT(n)  asm volatile("cp.async.wait_group %0;" :: "n"(n) : "memory")

#define LDSM_X4(r0, r1, r2, r3, addr) \
    asm volatile("ldmatrix.sync.aligned.m8n8.x4.shared.b16 {%0,%1,%2,%3}, [%4];" \
                 : "=r"(r0), "=r"(r1), "=r"(r2), "=r"(r3) : "r"(addr))
#define LDSM_X2(r0, r1, addr) \
    asm volatile("ldmatrix.sync.aligned.m8n8.x2.shared.b16 {%0,%1}, [%2];" \
                 : "=r"(r0), "=r"(r1) : "r"(addr))

#define MMA16816(c, a, b) \
    asm volatile("mma.sync.aligned.m16n8k16.row.col.f32.bf16.bf16.f32 " \
                 "{%0,%1,%2,%3}, {%4,%5,%6,%7}, {%8,%9}, {%0,%1,%2,%3};" \
                 : "+f"((c)[0]), "+f"((c)[1]), "+f"((c)[2]), "+f"((c)[3]) \
                 : "r"((a)[0]), "r"((a)[1]), "r"((a)[2]), "r"((a)[3]), \
                   "r"((b)[0]), "r"((b)[1]))

// ---------------------------------------------------------------------------
// Split fp32 -> (bf16 hi, bf16 lo) with lo = bf16(x - hi)
// ---------------------------------------------------------------------------
__global__ __launch_bounds__(256) void split_bf16(
    const float* __restrict__ src, __nv_bfloat16* __restrict__ hi,
    __nv_bfloat16* __restrict__ lo, int n4)
{
    int i = blockIdx.x * blockDim.x + threadIdx.x;
    if (i >= n4) return;
    float4 v = *(const float4*)(src + i * 4);
    __nv_bfloat16 h0 = __float2bfloat16(v.x), h1 = __float2bfloat16(v.y);
    __nv_bfloat16 h2 = __float2bfloat16(v.z), h3 = __float2bfloat16(v.w);
    __nv_bfloat162 hA; hA.x = h0; hA.y = h1;
    __nv_bfloat162 hB; hB.x = h2; hB.y = h3;
    __nv_bfloat162 lA, lB;
    lA.x = __float2bfloat16(v.x - __bfloat162float(h0));
    lA.y = __float2bfloat16(v.y - __bfloat162float(h1));
    lB.x = __float2bfloat16(v.z - __bfloat162float(h2));
    lB.y = __float2bfloat16(v.w - __bfloat162float(h3));
    *(__nv_bfloat162*)(hi + i * 4)     = hA;
    *(__nv_bfloat162*)(hi + i * 4 + 2) = hB;
    *(__nv_bfloat162*)(lo + i * 4)     = lA;
    *(__nv_bfloat162*)(lo + i * 4 + 2) = lB;
}

// ---------------------------------------------------------------------------
// bf16 mma.sync GEMM: C[m,n] = sum_k (Ah+Al)[m,k]*(Bh+Bl)[n,k] + bias[n]
// (drops Al*Bl ~ 2^-18 relative).
// CTA tile 128x128, BK=32, 256 threads = 8 warps (2M x 4N), warp tile 64x32.
// cp.async double-buffered smem; rows padded to 40 bf16 (80B) so ldmatrix
// pointer groups of 8 rows hit distinct banks (r*20 mod 32 all distinct).
// ---------------------------------------------------------------------------
#define KP 40                      // padded row length (bf16 elems)
#define TILE_B (128 * KP * 2)      // 10240 bytes per matrix tile
#define STAGE_B (4 * TILE_B)       // Ah|Al|Bh|Bl = 40960 bytes
#define GT_SMEM (2 * STAGE_B)      // double buffer = 81920 bytes

__global__ __launch_bounds__(256) void gemm_tc(
    const __nv_bfloat16* __restrict__ Ahg, const __nv_bfloat16* __restrict__ Alg,
    const __nv_bfloat16* __restrict__ Bhg, const __nv_bfloat16* __restrict__ Blg,
    const float* __restrict__ bias, float* __restrict__ C)
{
    extern __shared__ char dsm[];
    uint32_t sm = smem_u32(dsm);

    int tid  = threadIdx.x;
    int lane = tid & 31;
    int wid  = tid >> 5;
    int wm   = wid & 1;       // 0..1 -> 64-row band
    int wn   = wid >> 1;      // 0..3 -> 32-col band
    int bm   = blockIdx.y * 128;
    int bn   = blockIdx.x * 128;

    const char* gAh = (const char*)Ahg;
    const char* gAl = (const char*)Alg;
    const char* gBh = (const char*)Bhg;
    const char* gBl = (const char*)Blg;

    float acc[4][4][4];
#pragma unroll
    for (int i = 0; i < 4; i++)
#pragma unroll
        for (int j = 0; j < 4; j++)
#pragma unroll
            for (int c = 0; c < 4; c++) acc[i][j][c] = 0.f;

    // issue cp.async for one full stage (4 tiles of 128x32 bf16)
    auto load_stage = [&](int kt, int s) {
        int k0 = kt * 32;
        uint32_t sbase = sm + s * STAGE_B;
#pragma unroll
        for (int h = 0; h < 2; h++) {
            int idx = h * 256 + tid;       // 0..511
            int r   = idx >> 2;            // row 0..127
            int c   = (idx & 3) * 8;       // bf16 col 0,8,16,24
            uint32_t d = r * (KP * 2) + c * 2;
            size_t offA = ((size_t)(bm + r) * DD + k0 + c) * 2;
            size_t offB = ((size_t)(bn + r) * DD + k0 + c) * 2;
            CP_ASYNC16(sbase + 0 * TILE_B + d, gAh + offA);
            CP_ASYNC16(sbase + 1 * TILE_B + d, gAl + offA);
            CP_ASYNC16(sbase + 2 * TILE_B + d, gBh + offB);
            CP_ASYNC16(sbase + 3 * TILE_B + d, gBl + offB);
        }
    };

    auto compute_stage = [&](int s) {
        uint32_t sbase = sm + s * STAGE_B;
        int ar = lane & 15;
        int ac = (lane >> 4) * 8;
        int br = lane & 7;
        int bc = ((lane >> 3) & 1) * 8;
#pragma unroll
        for (int k16 = 0; k16 < 32; k16 += 16) {
            uint32_t aH[4][4], aL[4][4], bH[4][2], bL[4][2];
#pragma unroll
            for (int mt = 0; mt < 4; mt++) {
                uint32_t ad = sbase +
                    ((wm * 64 + mt * 16 + ar) * KP + k16 + ac) * 2;
                LDSM_X4(aH[mt][0], aH[mt][1], aH[mt][2], aH[mt][3], ad);
                LDSM_X4(aL[mt][0], aL[mt][1], aL[mt][2], aL[mt][3], ad + TILE_B);
            }
#pragma unroll
            for (int nt = 0; nt < 4; nt++) {
                uint32_t bd = sbase + 2 * TILE_B +
                    ((wn * 32 + nt * 8 + br) * KP + k16 + bc) * 2;
                LDSM_X2(bH[nt][0], bH[nt][1], bd);
                LDSM_X2(bL[nt][0], bL[nt][1], bd + TILE_B);
            }
#pragma unroll
            for (int mt = 0; mt < 4; mt++)
#pragma unroll
                for (int nt = 0; nt < 4; nt++) {
                    MMA16816(acc[mt][nt], aH[mt], bH[nt]);
                    MMA16816(acc[mt][nt], aH[mt], bL[nt]);
                    MMA16816(acc[mt][nt], aL[mt], bH[nt]);
                }
        }
    };

    const int NT = DD / 32;  // 32 k-tiles
    load_stage(0, 0);
    CP_COMMIT();
    for (int kt = 0; kt < NT; kt++) {
        if (kt + 1 < NT) {
            load_stage(kt + 1, (kt + 1) & 1);
            CP_COMMIT();
            CP_WAIT(1);      // current stage complete, next may be in flight
        } else {
            CP_WAIT(0);
        }
        __syncthreads();
        compute_stage(kt & 1);
        __syncthreads();     // protect buffer about to be overwritten
    }

    // epilogue: C fragment (gid = lane/4 row, tig = lane%4 col-pair)
    int gid = lane >> 2, tig = lane & 3;
#pragma unroll
    for (int mt = 0; mt < 4; mt++) {
#pragma unroll
        for (int nt = 0; nt < 4; nt++) {
            int m = bm + wm * 64 + mt * 16 + gid;
            int n = bn + wn * 32 + nt * 8 + tig * 2;
            float2 v0, v1;
            v0.x = acc[mt][nt][0] + bias[n];
            v0.y = acc[mt][nt][1] + bias[n + 1];
            v1.x = acc[mt][nt][2] + bias[n];
            v1.y = acc[mt][nt][3] + bias[n + 1];
            *(float2*)&C[(size_t)m * DD + n]       = v0;
            *(float2*)&C[(size_t)(m + 8) * DD + n] = v1;
        }
    }
}

// ---------------------------------------------------------------------------
// Causal flash attention, fp32, pair-split: 2 threads per query row,
// each owning 32 of the 64 head dims; scores combined via shfl_xor(1).
// Block = 128 threads = 64 query rows. K/V tiles 64x64 staged in smem.
// ---------------------------------------------------------------------------
__global__ __launch_bounds__(128) void attn_causal(
    const float* __restrict__ Q, const float* __restrict__ Kg,
    const float* __restrict__ Vg, float* __restrict__ Y)
{
    __shared__ __align__(16) float Ks[64][68];
    __shared__ __align__(16) float Vs[64][68];

    int qb  = blockIdx.x;
    int bh  = blockIdx.y;
    int b   = bh >> 4;
    int h   = bh & 15;
    int tid = threadIdx.x;
    int rl   = tid >> 1;        // local query row 0..63
    int half = tid & 1;         // which 32-dim half
    int qrow = qb * 64 + rl;

    const float scale = 0.125f;  // 1/sqrt(64)

    float q[32], o[32];
    const float* qp = Q + ((size_t)b * TT + qrow) * DD + h * HD + half * 32;
#pragma unroll
    for (int d = 0; d < 32; d++) { q[d] = qp[d] * scale; o[d] = 0.f; }
    float m = -1e30f, l = 0.f;

    for (int kb = 0; kb <= qb; kb++) {
        const float* kp = Kg + ((size_t)b * TT + kb * 64) * DD + h * HD;
        const float* vp = Vg + ((size_t)b * TT + kb * 64) * DD + h * HD;
#pragma unroll 4
        for (int i = tid; i < 64 * 64; i += 128) {
            int r = i >> 6, c = i & 63;
            Ks[r][c] = kp[(size_t)r * DD + c];
            Vs[r][c] = vp[(size_t)r * DD + c];
        }
        __syncthreads();

        int kbase = kb * 64;
#pragma unroll 1
        for (int c4 = 0; c4 < 4; c4++) {
            float s[16];
#pragma unroll
            for (int jj = 0; jj < 16; jj++) {
                int j = c4 * 16 + jj;
                float acc = 0.f;
#pragma unroll
                for (int d4 = 0; d4 < 8; d4++) {
                    float4 k4 = *(const float4*)&Ks[j][half * 32 + d4 * 4];
                    acc = fmaf(q[d4 * 4 + 0], k4.x, acc);
                    acc = fmaf(q[d4 * 4 + 1], k4.y, acc);
                    acc = fmaf(q[d4 * 4 + 2], k4.z, acc);
                    acc = fmaf(q[d4 * 4 + 3], k4.w, acc);
                }
                acc += __shfl_xor_sync(0xffffffffu, acc, 1);
                // chunk 0 of tile 0 always unmasked -> m finite before any
                // fully-masked chunk -> exp(-1e30 - m) == 0 exactly.
                s[jj] = (kbase + j <= qrow) ? acc : -1e30f;
            }
            float mnew = m;
#pragma unroll
            for (int jj = 0; jj < 16; jj++) mnew = fmaxf(mnew, s[jj]);
            float alpha = __expf(m - mnew);
            l *= alpha;
#pragma unroll
            for (int d = 0; d < 32; d++) o[d] *= alpha;
#pragma unroll
            for (int jj = 0; jj < 16; jj++) {
                int j = c4 * 16 + jj;
                float p = __expf(s[jj] - mnew);
                l += p;
#pragma unroll
                for (int d4 = 0; d4 < 8; d4++) {
                    float4 v4 = *(const float4*)&Vs[j][half * 32 + d4 * 4];
                    o[d4 * 4 + 0] = fmaf(p, v4.x, o[d4 * 4 + 0]);
                    o[d4 * 4 + 1] = fmaf(p, v4.y, o[d4 * 4 + 1]);
                    o[d4 * 4 + 2] = fmaf(p, v4.z, o[d4 * 4 + 2]);
                    o[d4 * 4 + 3] = fmaf(p, v4.w, o[d4 * 4 + 3]);
                }
            }
            m = mnew;
        }
        __syncthreads();
    }

    float inv = 1.f / l;
    float* yp = Y + ((size_t)b * TT + qrow) * DD + h * HD + half * 32;
#pragma unroll
    for (int d = 0; d < 32; d++) yp[d] = o[d] * inv;
}

// ---------------------------------------------------------------------------
// Launch: split x + weights -> 3 mma projections -> attention ->
// split y -> mma output projection. All graph-capturable.
// ---------------------------------------------------------------------------
extern "C" void kernel_launch(void* const* d_in, const int* in_sizes, int n_in,
                              void* d_out, int out_size)
{
    const float* x  = (const float*)d_in[0];
    const float* Wq = (const float*)d_in[1];
    const float* bq = (const float*)d_in[2];
    const float* Wk = (const float*)d_in[3];
    const float* bk = (const float*)d_in[4];
    const float* Wv = (const float*)d_in[5];
    const float* bv = (const float*)d_in[6];
    const float* Wp = (const float*)d_in[7];
    const float* bp = (const float*)d_in[8];
    float* out = (float*)d_out;

    float *qg, *kg, *vg, *yg;
    __nv_bfloat16 *xh, *xl, *wh, *wl;
    cudaGetSymbolAddress((void**)&qg, g_q);
    cudaGetSymbolAddress((void**)&kg, g_k);
    cudaGetSymbolAddress((void**)&vg, g_v);
    cudaGetSymbolAddress((void**)&yg, g_y);
    cudaGetSymbolAddress((void**)&xh, g_xh);
    cudaGetSymbolAddress((void**)&xl, g_xl);
    cudaGetSymbolAddress((void**)&wh, g_wh);
    cudaGetSymbolAddress((void**)&wl, g_wl);

    cudaFuncSetAttribute(gemm_tc, cudaFuncAttributeMaxDynamicSharedMemorySize, GT_SMEM);

    const int NX4 = BT * DD / 4;   // x / y elements as float4s
    const int NW4 = DD * DD / 4;   // one weight matrix

    // split x and all 4 weights to bf16 hi/lo
    split_bf16<<<NX4 / 256, 256>>>(x, xh, xl, NX4);
    split_bf16<<<NW4 / 256, 256>>>(Wq, wh + 0 * DD * DD, wl + 0 * DD * DD, NW4);
    split_bf16<<<NW4 / 256, 256>>>(Wk, wh + 1 * DD * DD, wl + 1 * DD * DD, NW4);
    split_bf16<<<NW4 / 256, 256>>>(Wv, wh + 2 * DD * DD, wl + 2 * DD * DD, NW4);
    split_bf16<<<NW4 / 256, 256>>>(Wp, wh + 3 * DD * DD, wl + 3 * DD * DD, NW4);

    dim3 gg(DD / 128, BT / 128);   // (8, 32)
    gemm_tc<<<gg, 256, GT_SMEM>>>(xh, xl, wh + 0 * DD * DD, wl + 0 * DD * DD, bq, qg);
    gemm_tc<<<gg, 256, GT_SMEM>>>(xh, xl, wh + 1 * DD * DD, wl + 1 * DD * DD, bk, kg);
    gemm_tc<<<gg, 256, GT_SMEM>>>(xh, xl, wh + 2 * DD * DD, wl + 2 * DD * DD, bv, vg);

    dim3 ga(TT / 64, BB * HH);     // (32, 32)
    attn_causal<<<ga, 128>>>(qg, kg, vg, yg);

    split_bf16<<<NX4 / 256, 256>>>(yg, xh, xl, NX4);
    gemm_tc<<<gg, 256, GT_SMEM>>>(xh, xl, wh + 3 * DD * DD, wl + 3 * DD * DD, bp, out);
}

// round 13
// speedup vs baseline: 3.8863x; 3.0259x over previous
#include <cuda_runtime.h>
#include <cuda_bf16.h>
#include <cstdint>

// Problem constants: B=2, T=2048, D=1024, H=16, HD=64
#define BB 2
#define TT 2048
#define DD 1024
#define HH 16
#define HD 64
#define BT (BB * TT)  // 4096 rows for projection GEMMs

// ---------------------------------------------------------------------------
// Scratch (__device__ globals; no allocs allowed). All bf16 hi/lo pairs.
// ---------------------------------------------------------------------------
__device__ __nv_bfloat16 g_xh[BT * DD];
__device__ __nv_bfloat16 g_xl[BT * DD];
__device__ __nv_bfloat16 g_wh[4 * DD * DD];
__device__ __nv_bfloat16 g_wl[4 * DD * DD];
__device__ __nv_bfloat16 g_qh[BT * DD];
__device__ __nv_bfloat16 g_ql[BT * DD];
__device__ __nv_bfloat16 g_kh[BT * DD];
__device__ __nv_bfloat16 g_kl[BT * DD];
__device__ __nv_bfloat16 g_vh[BT * DD];
__device__ __nv_bfloat16 g_vl[BT * DD];
__device__ __nv_bfloat16 g_yh[BT * DD];
__device__ __nv_bfloat16 g_yl[BT * DD];

// ---------------------------------------------------------------------------
// PTX helpers (base compute_103 target: mma.sync + ldmatrix + cp.async)
// ---------------------------------------------------------------------------
__device__ __forceinline__ uint32_t smem_u32(const void* p) {
    uint32_t a;
    asm("{ .reg .u64 t; cvta.to.shared.u64 t, %1; cvt.u32.u64 %0, t; }"
        : "=r"(a) : "l"(p));
    return a;
}

#define CP_ASYNC16(dst_u32, src_ptr) \
    asm volatile("cp.async.cg.shared.global [%0], [%1], 16;" \
                 :: "r"(dst_u32), "l"(src_ptr))
#define CP_COMMIT() asm volatile("cp.async.commit_group;" ::: "memory")
#define CP_WAIT(n)  asm volatile("cp.async.wait_group %0;" :: "n"(n) : "memory")

#define LDSM_X4(r0, r1, r2, r3, addr) \
    asm volatile("ldmatrix.sync.aligned.m8n8.x4.shared.b16 {%0,%1,%2,%3}, [%4];" \
                 : "=r"(r0), "=r"(r1), "=r"(r2), "=r"(r3) : "r"(addr))
#define LDSM_X2(r0, r1, addr) \
    asm volatile("ldmatrix.sync.aligned.m8n8.x2.shared.b16 {%0,%1}, [%2];" \
                 : "=r"(r0), "=r"(r1) : "r"(addr))
#define LDSM_X2_T(r0, r1, addr) \
    asm volatile("ldmatrix.sync.aligned.m8n8.x2.trans.shared.b16 {%0,%1}, [%2];" \
                 : "=r"(r0), "=r"(r1) : "r"(addr))

#define MMA16816(c, a, b) \
    asm volatile("mma.sync.aligned.m16n8k16.row.col.f32.bf16.bf16.f32 " \
                 "{%0,%1,%2,%3}, {%4,%5,%6,%7}, {%8,%9}, {%0,%1,%2,%3};" \
                 : "+f"((c)[0]), "+f"((c)[1]), "+f"((c)[2]), "+f"((c)[3]) \
                 : "r"((a)[0]), "r"((a)[1]), "r"((a)[2]), "r"((a)[3]), \
                   "r"((b)[0]), "r"((b)[1]))

__device__ __forceinline__ uint32_t pack2(float x, float y) {
    __nv_bfloat162 t = __float22bfloat162_rn(make_float2(x, y));
    return *reinterpret_cast<uint32_t*>(&t);
}
__device__ __forceinline__ uint32_t packlo(float x, float y, uint32_t hp) {
    __nv_bfloat162 h = *reinterpret_cast<__nv_bfloat162*>(&hp);
    return pack2(x - __bfloat162float(h.x), y - __bfloat162float(h.y));
}

// ---------------------------------------------------------------------------
// Split fp32 -> (bf16 hi, bf16 lo) with lo = bf16(x - hi)
// ---------------------------------------------------------------------------
__global__ __launch_bounds__(256) void split_bf16(
    const float* __restrict__ src, __nv_bfloat16* __restrict__ hi,
    __nv_bfloat16* __restrict__ lo, int n4)
{
    int i = blockIdx.x * blockDim.x + threadIdx.x;
    if (i >= n4) return;
    float4 v = *(const float4*)(src + i * 4);
    uint32_t hA = pack2(v.x, v.y), hB = pack2(v.z, v.w);
    uint32_t lA = packlo(v.x, v.y, hA), lB = packlo(v.z, v.w, hB);
    *(uint32_t*)(hi + i * 4)     = hA;
    *(uint32_t*)(hi + i * 4 + 2) = hB;
    *(uint32_t*)(lo + i * 4)     = lA;
    *(uint32_t*)(lo + i * 4 + 2) = lB;
}

// ---------------------------------------------------------------------------
// bf16 mma.sync GEMM: C[m,n] = sum_k (Ah+Al)[m,k]*(Bh+Bl)[n,k] + bias[n]
// MODE 0: fp32 output Cf.  MODE 1: bf16 hi/lo outputs Ch/Cl.
// CTA tile 128x128, BK=32, 256 threads = 8 warps (2M x 4N), warp tile 64x32.
// ---------------------------------------------------------------------------
#define KP 40                      // padded row length (bf16 elems)
#define TILE_B (128 * KP * 2)      // 10240 bytes per matrix tile
#define STAGE_B (4 * TILE_B)       // Ah|Al|Bh|Bl
#define GT_SMEM (2 * STAGE_B)      // double buffer = 81920 bytes

template <int MODE>
__global__ __launch_bounds__(256) void gemm_tc(
    const __nv_bfloat16* __restrict__ Ahg, const __nv_bfloat16* __restrict__ Alg,
    const __nv_bfloat16* __restrict__ Bhg, const __nv_bfloat16* __restrict__ Blg,
    const float* __restrict__ bias, float* __restrict__ Cf,
    __nv_bfloat16* __restrict__ Ch, __nv_bfloat16* __restrict__ Cl)
{
    extern __shared__ char dsm[];
    uint32_t sm = smem_u32(dsm);

    int tid  = threadIdx.x;
    int lane = tid & 31;
    int wid  = tid >> 5;
    int wm   = wid & 1;
    int wn   = wid >> 1;
    int bm   = blockIdx.y * 128;
    int bn   = blockIdx.x * 128;

    const char* gAh = (const char*)Ahg;
    const char* gAl = (const char*)Alg;
    const char* gBh = (const char*)Bhg;
    const char* gBl = (const char*)Blg;

    float acc[4][4][4];
#pragma unroll
    for (int i = 0; i < 4; i++)
#pragma unroll
        for (int j = 0; j < 4; j++)
#pragma unroll
            for (int c = 0; c < 4; c++) acc[i][j][c] = 0.f;

    auto load_stage = [&](int kt, int s) {
        int k0 = kt * 32;
        uint32_t sbase = sm + s * STAGE_B;
#pragma unroll
        for (int h = 0; h < 2; h++) {
            int idx = h * 256 + tid;
            int r   = idx >> 2;
            int c   = (idx & 3) * 8;
            uint32_t d = r * (KP * 2) + c * 2;
            size_t offA = ((size_t)(bm + r) * DD + k0 + c) * 2;
            size_t offB = ((size_t)(bn + r) * DD + k0 + c) * 2;
            CP_ASYNC16(sbase + 0 * TILE_B + d, gAh + offA);
            CP_ASYNC16(sbase + 1 * TILE_B + d, gAl + offA);
            CP_ASYNC16(sbase + 2 * TILE_B + d, gBh + offB);
            CP_ASYNC16(sbase + 3 * TILE_B + d, gBl + offB);
        }
    };

    auto compute_stage = [&](int s) {
        uint32_t sbase = sm + s * STAGE_B;
        int ar = lane & 15;
        int ac = (lane >> 4) * 8;
        int br = lane & 7;
        int bc = ((lane >> 3) & 1) * 8;
#pragma unroll
        for (int k16 = 0; k16 < 32; k16 += 16) {
            uint32_t aH[4][4], aL[4][4], bH[4][2], bL[4][2];
#pragma unroll
            for (int mt = 0; mt < 4; mt++) {
                uint32_t ad = sbase +
                    ((wm * 64 + mt * 16 + ar) * KP + k16 + ac) * 2;
                LDSM_X4(aH[mt][0], aH[mt][1], aH[mt][2], aH[mt][3], ad);
                LDSM_X4(aL[mt][0], aL[mt][1], aL[mt][2], aL[mt][3], ad + TILE_B);
            }
#pragma unroll
            for (int nt = 0; nt < 4; nt++) {
                uint32_t bd = sbase + 2 * TILE_B +
                    ((wn * 32 + nt * 8 + br) * KP + k16 + bc) * 2;
                LDSM_X2(bH[nt][0], bH[nt][1], bd);
                LDSM_X2(bL[nt][0], bL[nt][1], bd + TILE_B);
            }
#pragma unroll
            for (int mt = 0; mt < 4; mt++)
#pragma unroll
                for (int nt = 0; nt < 4; nt++) {
                    MMA16816(acc[mt][nt], aH[mt], bH[nt]);
                    MMA16816(acc[mt][nt], aH[mt], bL[nt]);
                    MMA16816(acc[mt][nt], aL[mt], bH[nt]);
                }
        }
    };

    const int NT = DD / 32;
    load_stage(0, 0);
    CP_COMMIT();
    for (int kt = 0; kt < NT; kt++) {
        if (kt + 1 < NT) {
            load_stage(kt + 1, (kt + 1) & 1);
            CP_COMMIT();
            CP_WAIT(1);
        } else {
            CP_WAIT(0);
        }
        __syncthreads();
        compute_stage(kt & 1);
        __syncthreads();
    }

    int gid = lane >> 2, tig = lane & 3;
#pragma unroll
    for (int mt = 0; mt < 4; mt++) {
#pragma unroll
        for (int nt = 0; nt < 4; nt++) {
            int m = bm + wm * 64 + mt * 16 + gid;
            int n = bn + wn * 32 + nt * 8 + tig * 2;
            float bx = bias[n], by = bias[n + 1];
            float v0x = acc[mt][nt][0] + bx, v0y = acc[mt][nt][1] + by;
            float v1x = acc[mt][nt][2] + bx, v1y = acc[mt][nt][3] + by;
            if (MODE == 0) {
                *(float2*)&Cf[(size_t)m * DD + n]       = make_float2(v0x, v0y);
                *(float2*)&Cf[(size_t)(m + 8) * DD + n] = make_float2(v1x, v1y);
            } else {
                uint32_t h0 = pack2(v0x, v0y);
                uint32_t h1 = pack2(v1x, v1y);
                *(uint32_t*)&Ch[(size_t)m * DD + n]       = h0;
                *(uint32_t*)&Ch[(size_t)(m + 8) * DD + n] = h1;
                *(uint32_t*)&Cl[(size_t)m * DD + n]       = packlo(v0x, v0y, h0);
                *(uint32_t*)&Cl[(size_t)(m + 8) * DD + n] = packlo(v1x, v1y, h1);
            }
        }
    }
}

// ---------------------------------------------------------------------------
// Tensor-core causal flash attention.
// Block = 128 threads (4 warps); block owns 64 q-rows of one (b,h).
// Warp w: 16 q-rows. QK^T: 3-term hi/lo bf16 mma (K via ldmatrix.x2).
// Softmax in C-fragment (quad shuffles). P repacked in-register to A-frag,
// split hi/lo. PV: 3-term mma with V via ldmatrix.x2.trans.
// K/V tiles cp.async double-buffered. Output written as bf16 hi/lo.
// ---------------------------------------------------------------------------
#define SP 72                           // smem row stride (bf16 elems)
#define ATILE_BY (64 * SP * 2)          // 9216 B per 64x64 tile
#define ASTAGE_BY (4 * ATILE_BY)        // Kh|Kl|Vh|Vl = 36864 B
#define ATT_SMEM (2 * ATILE_BY + 2 * ASTAGE_BY)  // Q tiles + 2 stages = 92160 B

__global__ __launch_bounds__(128) void attn_mma(
    const __nv_bfloat16* __restrict__ Qh, const __nv_bfloat16* __restrict__ Ql,
    const __nv_bfloat16* __restrict__ Kh, const __nv_bfloat16* __restrict__ Kl,
    const __nv_bfloat16* __restrict__ Vh, const __nv_bfloat16* __restrict__ Vl,
    __nv_bfloat16* __restrict__ Yh, __nv_bfloat16* __restrict__ Yl)
{
    extern __shared__ char dsm[];
    uint32_t sm = smem_u32(dsm);
    int qb = blockIdx.x, bh = blockIdx.y;
    int b = bh >> 4, h = bh & 15;
    int tid = threadIdx.x, lane = tid & 31, w = tid >> 5;
    int gid = lane >> 2, tig = lane & 3;

    const size_t hbase = (size_t)b * TT * DD + h * 64;
    uint32_t uQh = sm, uQl = sm + ATILE_BY;

    auto tile_load = [&](uint32_t dst, const __nv_bfloat16* src) {
#pragma unroll
        for (int it = 0; it < 4; it++) {
            int idx = it * 128 + tid;
            int r = idx >> 3, c8 = (idx & 7) * 8;
            CP_ASYNC16(dst + (r * SP + c8) * 2, src + (size_t)r * DD + c8);
        }
    };
    auto stage_load = [&](int kt, int s) {
        uint32_t sb = sm + 2 * ATILE_BY + s * ASTAGE_BY;
        const size_t rb = hbase + (size_t)(kt * 64) * DD;
        tile_load(sb,                 Kh + rb);
        tile_load(sb + ATILE_BY,      Kl + rb);
        tile_load(sb + 2 * ATILE_BY,  Vh + rb);
        tile_load(sb + 3 * ATILE_BY,  Vl + rb);
    };

    {
        const size_t rb = hbase + (size_t)(qb * 64) * DD;
        tile_load(uQh, Qh + rb);
        tile_load(uQl, Ql + rb);
    }
    stage_load(0, 0);
    CP_COMMIT();
    CP_WAIT(0);
    __syncthreads();

    // persistent Q fragments (verified A-frag recipe)
    uint32_t aQh[4][4], aQl[4][4];
    {
        int ar = lane & 15, ac = (lane >> 4) * 8;
#pragma unroll
        for (int k = 0; k < 4; k++) {
            uint32_t ad = uQh + ((w * 16 + ar) * SP + k * 16 + ac) * 2;
            LDSM_X4(aQh[k][0], aQh[k][1], aQh[k][2], aQh[k][3], ad);
            LDSM_X4(aQl[k][0], aQl[k][1], aQl[k][2], aQl[k][3], ad + ATILE_BY);
        }
    }

    float o[8][4];
#pragma unroll
    for (int n = 0; n < 8; n++)
#pragma unroll
        for (int j = 0; j < 4; j++) o[n][j] = 0.f;
    float m0 = -1e30f, m1 = -1e30f, l0 = 0.f, l1 = 0.f;
    int row0 = qb * 64 + w * 16 + gid, row1 = row0 + 8;

    for (int kt = 0; kt <= qb; kt++) {
        if (kt < qb) { stage_load(kt + 1, (kt + 1) & 1); CP_COMMIT(); CP_WAIT(1); }
        else         { CP_WAIT(0); }
        __syncthreads();

        uint32_t sb  = sm + 2 * ATILE_BY + (kt & 1) * ASTAGE_BY;
        uint32_t uKh = sb, uKl = sb + ATILE_BY;
        uint32_t uVh = sb + 2 * ATILE_BY, uVl = sb + 3 * ATILE_BY;

        // ---- scores S = (Qh+Ql)(Kh+Kl)^T (3 terms), fp32 accum
        float c[8][4];
#pragma unroll
        for (int n = 0; n < 8; n++)
#pragma unroll
            for (int j = 0; j < 4; j++) c[n][j] = 0.f;
        {
            int br = lane & 7, bc = ((lane >> 3) & 1) * 8;
            uint32_t bH[2], bL[2];
#pragma unroll
            for (int k = 0; k < 4; k++)
#pragma unroll
                for (int n = 0; n < 8; n++) {
                    uint32_t kd = ((n * 8 + br) * SP + k * 16 + bc) * 2;
                    LDSM_X2(bH[0], bH[1], uKh + kd);
                    LDSM_X2(bL[0], bL[1], uKl + kd);
                    MMA16816(c[n], aQh[k], bH);
                    MMA16816(c[n], aQh[k], bL);
                    MMA16816(c[n], aQl[k], bH);
                }
        }

        // ---- scale + causal mask (diag tile only)
#pragma unroll
        for (int n = 0; n < 8; n++)
#pragma unroll
            for (int j = 0; j < 4; j++) c[n][j] *= 0.125f;
        if (kt == qb) {
#pragma unroll
            for (int n = 0; n < 8; n++) {
                int col = kt * 64 + n * 8 + tig * 2;
                if (col     > row0) c[n][0] = -1e30f;
                if (col + 1 > row0) c[n][1] = -1e30f;
                if (col     > row1) c[n][2] = -1e30f;
                if (col + 1 > row1) c[n][3] = -1e30f;
            }
        }

        // ---- online softmax (rows gid / gid+8; quad = lanes sharing gid)
        float t0 = -1e30f, t1 = -1e30f;
#pragma unroll
        for (int n = 0; n < 8; n++) {
            t0 = fmaxf(t0, fmaxf(c[n][0], c[n][1]));
            t1 = fmaxf(t1, fmaxf(c[n][2], c[n][3]));
        }
        t0 = fmaxf(t0, __shfl_xor_sync(0xffffffffu, t0, 1));
        t0 = fmaxf(t0, __shfl_xor_sync(0xffffffffu, t0, 2));
        t1 = fmaxf(t1, __shfl_xor_sync(0xffffffffu, t1, 1));
        t1 = fmaxf(t1, __shfl_xor_sync(0xffffffffu, t1, 2));
        float m0n = fmaxf(m0, t0), m1n = fmaxf(m1, t1);
        float a0 = __expf(m0 - m0n), a1 = __expf(m1 - m1n);
        l0 *= a0; l1 *= a1;
#pragma unroll
        for (int n = 0; n < 8; n++) {
            o[n][0] *= a0; o[n][1] *= a0; o[n][2] *= a1; o[n][3] *= a1;
        }
#pragma unroll
        for (int n = 0; n < 8; n++) {
            c[n][0] = __expf(c[n][0] - m0n); c[n][1] = __expf(c[n][1] - m0n);
            c[n][2] = __expf(c[n][2] - m1n); c[n][3] = __expf(c[n][3] - m1n);
            l0 += c[n][0] + c[n][1];
            l1 += c[n][2] + c[n][3];
        }
        m0 = m0n; m1 = m1n;

        // ---- PV: O += (Ph+Pl)(Vh+Vl) (3 terms). P packed C->A in regs.
        {
            uint32_t bH[2], bL[2];
            int vr = lane & 15;
#pragma unroll
            for (int kk = 0; kk < 4; kk++) {
                uint32_t aPh[4], aPl[4];
                aPh[0] = pack2(c[2*kk][0],     c[2*kk][1]);
                aPh[1] = pack2(c[2*kk][2],     c[2*kk][3]);
                aPh[2] = pack2(c[2*kk+1][0],   c[2*kk+1][1]);
                aPh[3] = pack2(c[2*kk+1][2],   c[2*kk+1][3]);
                aPl[0] = packlo(c[2*kk][0],    c[2*kk][1],   aPh[0]);
                aPl[1] = packlo(c[2*kk][2],    c[2*kk][3],   aPh[1]);
                aPl[2] = packlo(c[2*kk+1][0],  c[2*kk+1][1], aPh[2]);
                aPl[3] = packlo(c[2*kk+1][2],  c[2*kk+1][3], aPh[3]);
#pragma unroll
                for (int nd = 0; nd < 8; nd++) {
                    uint32_t vd = ((kk * 16 + vr) * SP + nd * 8) * 2;
                    LDSM_X2_T(bH[0], bH[1], uVh + vd);
                    LDSM_X2_T(bL[0], bL[1], uVl + vd);
                    MMA16816(o[nd], aPh, bH);
                    MMA16816(o[nd], aPh, bL);
                    MMA16816(o[nd], aPl, bH);
                }
            }
        }
        __syncthreads();
    }

    // ---- finalize: reduce l over quad, normalize, emit bf16 hi/lo
    l0 += __shfl_xor_sync(0xffffffffu, l0, 1);
    l0 += __shfl_xor_sync(0xffffffffu, l0, 2);
    l1 += __shfl_xor_sync(0xffffffffu, l1, 1);
    l1 += __shfl_xor_sync(0xffffffffu, l1, 2);
    float i0 = 1.f / l0, i1 = 1.f / l1;
#pragma unroll
    for (int nd = 0; nd < 8; nd++) {
        int col = nd * 8 + tig * 2;
        float y0 = o[nd][0] * i0, y1 = o[nd][1] * i0;
        float z0 = o[nd][2] * i1, z1 = o[nd][3] * i1;
        uint32_t hp0 = pack2(y0, y1), hp1 = pack2(z0, z1);
        size_t off0 = hbase + (size_t)row0 * DD + col;
        size_t off1 = hbase + (size_t)row1 * DD + col;
        *(uint32_t*)&Yh[off0] = hp0;
        *(uint32_t*)&Yh[off1] = hp1;
        *(uint32_t*)&Yl[off0] = packlo(y0, y1, hp0);
        *(uint32_t*)&Yl[off1] = packlo(z0, z1, hp1);
    }
}

// ---------------------------------------------------------------------------
// Launch: splits -> 3 proj GEMMs (bf16 hi/lo out) -> mma attention ->
// output GEMM (fp32 out). All graph-capturable, no allocs.
// ---------------------------------------------------------------------------
extern "C" void kernel_launch(void* const* d_in, const int* in_sizes, int n_in,
                              void* d_out, int out_size)
{
    const float* x  = (const float*)d_in[0];
    const float* Wq = (const float*)d_in[1];
    const float* bq = (const float*)d_in[2];
    const float* Wk = (const float*)d_in[3];
    const float* bk = (const float*)d_in[4];
    const float* Wv = (const float*)d_in[5];
    const float* bv = (const float*)d_in[6];
    const float* Wp = (const float*)d_in[7];
    const float* bp = (const float*)d_in[8];
    float* out = (float*)d_out;

    __nv_bfloat16 *xh, *xl, *wh, *wl, *qh, *ql, *kh, *kl, *vh, *vl, *yh, *yl;
    cudaGetSymbolAddress((void**)&xh, g_xh);
    cudaGetSymbolAddress((void**)&xl, g_xl);
    cudaGetSymbolAddress((void**)&wh, g_wh);
    cudaGetSymbolAddress((void**)&wl, g_wl);
    cudaGetSymbolAddress((void**)&qh, g_qh);
    cudaGetSymbolAddress((void**)&ql, g_ql);
    cudaGetSymbolAddress((void**)&kh, g_kh);
    cudaGetSymbolAddress((void**)&kl, g_kl);
    cudaGetSymbolAddress((void**)&vh, g_vh);
    cudaGetSymbolAddress((void**)&vl, g_vl);
    cudaGetSymbolAddress((void**)&yh, g_yh);
    cudaGetSymbolAddress((void**)&yl, g_yl);

    cudaFuncSetAttribute(gemm_tc<0>, cudaFuncAttributeMaxDynamicSharedMemorySize, GT_SMEM);
    cudaFuncSetAttribute(gemm_tc<1>, cudaFuncAttributeMaxDynamicSharedMemorySize, GT_SMEM);
    cudaFuncSetAttribute(attn_mma, cudaFuncAttributeMaxDynamicSharedMemorySize, ATT_SMEM);

    const int NX4 = BT * DD / 4;
    const int NW4 = DD * DD / 4;

    split_bf16<<<NX4 / 256, 256>>>(x, xh, xl, NX4);
    split_bf16<<<NW4 / 256, 256>>>(Wq, wh + 0 * DD * DD, wl + 0 * DD * DD, NW4);
    split_bf16<<<NW4 / 256, 256>>>(Wk, wh + 1 * DD * DD, wl + 1 * DD * DD, NW4);
    split_bf16<<<NW4 / 256, 256>>>(Wv, wh + 2 * DD * DD, wl + 2 * DD * DD, NW4);
    split_bf16<<<NW4 / 256, 256>>>(Wp, wh + 3 * DD * DD, wl + 3 * DD * DD, NW4);

    dim3 gg(DD / 128, BT / 128);   // (8, 32)
    gemm_tc<1><<<gg, 256, GT_SMEM>>>(xh, xl, wh + 0 * DD * DD, wl + 0 * DD * DD, bq,
                                     nullptr, qh, ql);
    gemm_tc<1><<<gg, 256, GT_SMEM>>>(xh, xl, wh + 1 * DD * DD, wl + 1 * DD * DD, bk,
                                     nullptr, kh, kl);
    gemm_tc<1><<<gg, 256, GT_SMEM>>>(xh, xl, wh + 2 * DD * DD, wl + 2 * DD * DD, bv,
                                     nullptr, vh, vl);

    dim3 ga(TT / 64, BB * HH);     // (32, 32)
    attn_mma<<<ga, 128, ATT_SMEM>>>(qh, ql, kh, kl, vh, vl, yh, yl);

    gemm_tc<0><<<gg, 256, GT_SMEM>>>(yh, yl, wh + 3 * DD * DD, wl + 3 * DD * DD, bp,
                                     out, nullptr, nullptr);
}

// round 16
// speedup vs baseline: 3.9240x; 1.0097x over previous
#include <cuda_runtime.h>
#include <cuda_bf16.h>
#include <cstdint>

// Problem constants: B=2, T=2048, D=1024, H=16, HD=64
#define BB 2
#define TT 2048
#define DD 1024
#define HH 16
#define HD 64
#define BT (BB * TT)  // 4096 rows for projection GEMMs

// ---------------------------------------------------------------------------
// Scratch (__device__ globals; no allocs allowed). All bf16 hi/lo pairs.
// ---------------------------------------------------------------------------
__device__ __nv_bfloat16 g_xh[BT * DD];
__device__ __nv_bfloat16 g_xl[BT * DD];
__device__ __nv_bfloat16 g_wh[4 * DD * DD];
__device__ __nv_bfloat16 g_wl[4 * DD * DD];
__device__ __nv_bfloat16 g_qh[BT * DD];
__device__ __nv_bfloat16 g_ql[BT * DD];
__device__ __nv_bfloat16 g_kh[BT * DD];
__device__ __nv_bfloat16 g_kl[BT * DD];
__device__ __nv_bfloat16 g_vh[BT * DD];
__device__ __nv_bfloat16 g_vl[BT * DD];
__device__ __nv_bfloat16 g_yh[BT * DD];
__device__ __nv_bfloat16 g_yl[BT * DD];

// ---------------------------------------------------------------------------
// PTX helpers (base compute_103 target: mma.sync + ldmatrix + cp.async)
// ---------------------------------------------------------------------------
__device__ __forceinline__ uint32_t smem_u32(const void* p) {
    uint32_t a;
    asm("{ .reg .u64 t; cvta.to.shared.u64 t, %1; cvt.u32.u64 %0, t; }"
        : "=r"(a) : "l"(p));
    return a;
}

#define CP_ASYNC16(dst_u32, src_ptr) \
    asm volatile("cp.async.cg.shared.global [%0], [%1], 16;" \
                 :: "r"(dst_u32), "l"(src_ptr))
#define CP_COMMIT() asm volatile("cp.async.commit_group;" ::: "memory")
#define CP_WAIT(n)  asm volatile("cp.async.wait_group %0;" :: "n"(n) : "memory")

#define LDSM_X4(r0, r1, r2, r3, addr) \
    asm volatile("ldmatrix.sync.aligned.m8n8.x4.shared.b16 {%0,%1,%2,%3}, [%4];" \
                 : "=r"(r0), "=r"(r1), "=r"(r2), "=r"(r3) : "r"(addr))
#define LDSM_X2(r0, r1, addr) \
    asm volatile("ldmatrix.sync.aligned.m8n8.x2.shared.b16 {%0,%1}, [%2];" \
                 : "=r"(r0), "=r"(r1) : "r"(addr))
#define LDSM_X2_T(r0, r1, addr) \
    asm volatile("ldmatrix.sync.aligned.m8n8.x2.trans.shared.b16 {%0,%1}, [%2];" \
                 : "=r"(r0), "=r"(r1) : "r"(addr))

#define MMA16816(c, a, b) \
    asm volatile("mma.sync.aligned.m16n8k16.row.col.f32.bf16.bf16.f32 " \
                 "{%0,%1,%2,%3}, {%4,%5,%6,%7}, {%8,%9}, {%0,%1,%2,%3};" \
                 : "+f"((c)[0]), "+f"((c)[1]), "+f"((c)[2]), "+f"((c)[3]) \
                 : "r"((a)[0]), "r"((a)[1]), "r"((a)[2]), "r"((a)[3]), \
                   "r"((b)[0]), "r"((b)[1]))

__device__ __forceinline__ uint32_t pack2(float x, float y) {
    __nv_bfloat162 t = __float22bfloat162_rn(make_float2(x, y));
    return *reinterpret_cast<uint32_t*>(&t);
}
__device__ __forceinline__ uint32_t packlo(float x, float y, uint32_t hp) {
    __nv_bfloat162 h = *reinterpret_cast<__nv_bfloat162*>(&hp);
    return pack2(x - __bfloat162float(h.x), y - __bfloat162float(h.y));
}

// ---------------------------------------------------------------------------
// Split fp32 -> (bf16 hi, bf16 lo) with lo = bf16(x - hi)
// ---------------------------------------------------------------------------
__global__ __launch_bounds__(256) void split_bf16(
    const float* __restrict__ src, __nv_bfloat16* __restrict__ hi,
    __nv_bfloat16* __restrict__ lo, int n4)
{
    int i = blockIdx.x * blockDim.x + threadIdx.x;
    if (i >= n4) return;
    float4 v = *(const float4*)(src + i * 4);
    uint32_t hA = pack2(v.x, v.y), hB = pack2(v.z, v.w);
    uint32_t lA = packlo(v.x, v.y, hA), lB = packlo(v.z, v.w, hB);
    *(uint32_t*)(hi + i * 4)     = hA;
    *(uint32_t*)(hi + i * 4 + 2) = hB;
    *(uint32_t*)(lo + i * 4)     = lA;
    *(uint32_t*)(lo + i * 4 + 2) = lB;
}

// ---------------------------------------------------------------------------
// GEMM core (audited body, unchanged math): CTA tile 128x128, BK=32,
// 256 threads = 8 warps (2M x 4N), warp tile 64x32, cp.async double-buffered.
// Accumulates (Ah+Al)(Bh+Bl)^T via 3 mma terms.
// ---------------------------------------------------------------------------
#define KP 40                      // padded row length (bf16 elems)
#define TILE_B (128 * KP * 2)      // 10240 bytes per matrix tile
#define STAGE_B (4 * TILE_B)       // Ah|Al|Bh|Bl
#define GT_SMEM (2 * STAGE_B)      // double buffer = 81920 bytes

struct GemmCore {
    uint32_t sm;
    int tid, lane, wid, wm, wn, bm;
    const char *gAh, *gAl, *gBh, *gBl;  // B pointers already offset to matrix + bn row 0
    int bn_row;                          // row offset within B (local bn)
    float acc[4][4][4];

    __device__ __forceinline__ void init(uint32_t sm_, int bm_, int bn_row_,
        const __nv_bfloat16* Ah, const __nv_bfloat16* Al,
        const __nv_bfloat16* Bh, const __nv_bfloat16* Bl)
    {
        sm = sm_; tid = threadIdx.x; lane = tid & 31; wid = tid >> 5;
        wm = wid & 1; wn = wid >> 1; bm = bm_; bn_row = bn_row_;
        gAh = (const char*)Ah; gAl = (const char*)Al;
        gBh = (const char*)Bh; gBl = (const char*)Bl;
#pragma unroll
        for (int i = 0; i < 4; i++)
#pragma unroll
            for (int j = 0; j < 4; j++)
#pragma unroll
                for (int c = 0; c < 4; c++) acc[i][j][c] = 0.f;
    }

    __device__ __forceinline__ void load_stage(int kt, int s) {
        int k0 = kt * 32;
        uint32_t sbase = sm + s * STAGE_B;
#pragma unroll
        for (int h = 0; h < 2; h++) {
            int idx = h * 256 + tid;
            int r   = idx >> 2;
            int c   = (idx & 3) * 8;
            uint32_t d = r * (KP * 2) + c * 2;
            size_t offA = ((size_t)(bm + r) * DD + k0 + c) * 2;
            size_t offB = ((size_t)(bn_row + r) * DD + k0 + c) * 2;
            CP_ASYNC16(sbase + 0 * TILE_B + d, gAh + offA);
            CP_ASYNC16(sbase + 1 * TILE_B + d, gAl + offA);
            CP_ASYNC16(sbase + 2 * TILE_B + d, gBh + offB);
            CP_ASYNC16(sbase + 3 * TILE_B + d, gBl + offB);
        }
    }

    __device__ __forceinline__ void compute_stage(int s) {
        uint32_t sbase = sm + s * STAGE_B;
        int ar = lane & 15;
        int ac = (lane >> 4) * 8;
        int br = lane & 7;
        int bc = ((lane >> 3) & 1) * 8;
#pragma unroll
        for (int k16 = 0; k16 < 32; k16 += 16) {
            uint32_t aH[4][4], aL[4][4], bH[4][2], bL[4][2];
#pragma unroll
            for (int mt = 0; mt < 4; mt++) {
                uint32_t ad = sbase +
                    ((wm * 64 + mt * 16 + ar) * KP + k16 + ac) * 2;
                LDSM_X4(aH[mt][0], aH[mt][1], aH[mt][2], aH[mt][3], ad);
                LDSM_X4(aL[mt][0], aL[mt][1], aL[mt][2], aL[mt][3], ad + TILE_B);
            }
#pragma unroll
            for (int nt = 0; nt < 4; nt++) {
                uint32_t bd = sbase + 2 * TILE_B +
                    ((wn * 32 + nt * 8 + br) * KP + k16 + bc) * 2;
                LDSM_X2(bH[nt][0], bH[nt][1], bd);
                LDSM_X2(bL[nt][0], bL[nt][1], bd + TILE_B);
            }
#pragma unroll
            for (int mt = 0; mt < 4; mt++)
#pragma unroll
                for (int nt = 0; nt < 4; nt++) {
                    MMA16816(acc[mt][nt], aH[mt], bH[nt]);
                    MMA16816(acc[mt][nt], aH[mt], bL[nt]);
                    MMA16816(acc[mt][nt], aL[mt], bH[nt]);
                }
        }
    }

    __device__ __forceinline__ void run() {
        const int NT = DD / 32;
        load_stage(0, 0);
        CP_COMMIT();
        for (int kt = 0; kt < NT; kt++) {
            if (kt + 1 < NT) {
                load_stage(kt + 1, (kt + 1) & 1);
                CP_COMMIT();
                CP_WAIT(1);
            } else {
                CP_WAIT(0);
            }
            __syncthreads();
            compute_stage(kt & 1);
            __syncthreads();
        }
    }
};

// ---------------------------------------------------------------------------
// Fused QKV projection GEMM: grid (24, 32). blockIdx.x selects matrix
// (x>>3: 0=Q,1=K,2=V) and column tile within it (x&7). One launch fills
// the machine (768 CTAs) instead of three 256-CTA launches.
// ---------------------------------------------------------------------------
__global__ __launch_bounds__(256) void gemm_qkv(
    const __nv_bfloat16* __restrict__ Ahg, const __nv_bfloat16* __restrict__ Alg,
    const __nv_bfloat16* __restrict__ Whg, const __nv_bfloat16* __restrict__ Wlg,
    const float* __restrict__ bq, const float* __restrict__ bk,
    const float* __restrict__ bv,
    __nv_bfloat16* __restrict__ Qh, __nv_bfloat16* __restrict__ Ql,
    __nv_bfloat16* __restrict__ Kh, __nv_bfloat16* __restrict__ Kl,
    __nv_bfloat16* __restrict__ Vh, __nv_bfloat16* __restrict__ Vl)
{
    extern __shared__ char dsm[];
    int mat = blockIdx.x >> 3;            // 0=Q, 1=K, 2=V
    int bn  = (blockIdx.x & 7) * 128;     // column tile within matrix
    int bm  = blockIdx.y * 128;

    const float* bias = (mat == 0) ? bq : (mat == 1) ? bk : bv;
    __nv_bfloat16* Ch = (mat == 0) ? Qh : (mat == 1) ? Kh : Vh;
    __nv_bfloat16* Cl = (mat == 0) ? Ql : (mat == 1) ? Kl : Vl;

    GemmCore g;
    g.init(smem_u32(dsm), bm, bn,
           Ahg, Alg, Whg + (size_t)mat * DD * DD, Wlg + (size_t)mat * DD * DD);
    g.run();

    int gid = g.lane >> 2, tig = g.lane & 3;
#pragma unroll
    for (int mt = 0; mt < 4; mt++) {
#pragma unroll
        for (int nt = 0; nt < 4; nt++) {
            int m = bm + g.wm * 64 + mt * 16 + gid;
            int n = bn + g.wn * 32 + nt * 8 + tig * 2;
            float bx = bias[n], by = bias[n + 1];
            float v0x = g.acc[mt][nt][0] + bx, v0y = g.acc[mt][nt][1] + by;
            float v1x = g.acc[mt][nt][2] + bx, v1y = g.acc[mt][nt][3] + by;
            uint32_t h0 = pack2(v0x, v0y);
            uint32_t h1 = pack2(v1x, v1y);
            *(uint32_t*)&Ch[(size_t)m * DD + n]       = h0;
            *(uint32_t*)&Ch[(size_t)(m + 8) * DD + n] = h1;
            *(uint32_t*)&Cl[(size_t)m * DD + n]       = packlo(v0x, v0y, h0);
            *(uint32_t*)&Cl[(size_t)(m + 8) * DD + n] = packlo(v1x, v1y, h1);
        }
    }
}

// ---------------------------------------------------------------------------
// Output projection GEMM: fp32 result + bias.
// ---------------------------------------------------------------------------
__global__ __launch_bounds__(256) void gemm_out(
    const __nv_bfloat16* __restrict__ Ahg, const __nv_bfloat16* __restrict__ Alg,
    const __nv_bfloat16* __restrict__ Bhg, const __nv_bfloat16* __restrict__ Blg,
    const float* __restrict__ bias, float* __restrict__ Cf)
{
    extern __shared__ char dsm[];
    int bn = blockIdx.x * 128;
    int bm = blockIdx.y * 128;

    GemmCore g;
    g.init(smem_u32(dsm), bm, bn, Ahg, Alg, Bhg, Blg);
    g.run();

    int gid = g.lane >> 2, tig = g.lane & 3;
#pragma unroll
    for (int mt = 0; mt < 4; mt++) {
#pragma unroll
        for (int nt = 0; nt < 4; nt++) {
            int m = bm + g.wm * 64 + mt * 16 + gid;
            int n = bn + g.wn * 32 + nt * 8 + tig * 2;
            float bx = bias[n], by = bias[n + 1];
            *(float2*)&Cf[(size_t)m * DD + n] =
                make_float2(g.acc[mt][nt][0] + bx, g.acc[mt][nt][1] + by);
            *(float2*)&Cf[(size_t)(m + 8) * DD + n] =
                make_float2(g.acc[mt][nt][2] + bx, g.acc[mt][nt][3] + by);
        }
    }
}

// ---------------------------------------------------------------------------
// Tensor-core causal flash attention (audited R13 design, unchanged except
// LPT scheduling: qb reversed so longest blocks launch first).
// ---------------------------------------------------------------------------
#define SP 72                           // smem row stride (bf16 elems)
#define ATILE_BY (64 * SP * 2)          // 9216 B per 64x64 tile
#define ASTAGE_BY (4 * ATILE_BY)        // Kh|Kl|Vh|Vl = 36864 B
#define ATT_SMEM (2 * ATILE_BY + 2 * ASTAGE_BY)  // Q tiles + 2 stages = 92160 B

__global__ __launch_bounds__(128) void attn_mma(
    const __nv_bfloat16* __restrict__ Qh, const __nv_bfloat16* __restrict__ Ql,
    const __nv_bfloat16* __restrict__ Kh, const __nv_bfloat16* __restrict__ Kl,
    const __nv_bfloat16* __restrict__ Vh, const __nv_bfloat16* __restrict__ Vl,
    __nv_bfloat16* __restrict__ Yh, __nv_bfloat16* __restrict__ Yl)
{
    extern __shared__ char dsm[];
    uint32_t sm = smem_u32(dsm);
    // LPT: longest blocks (largest qb) first
    int qb = (int)gridDim.x - 1 - (int)blockIdx.x;
    int bh = blockIdx.y;
    int b = bh >> 4, h = bh & 15;
    int tid = threadIdx.x, lane = tid & 31, w = tid >> 5;
    int gid = lane >> 2, tig = lane & 3;

    const size_t hbase = (size_t)b * TT * DD + h * 64;
    uint32_t uQh = sm, uQl = sm + ATILE_BY;

    auto tile_load = [&](uint32_t dst, const __nv_bfloat16* src) {
#pragma unroll
        for (int it = 0; it < 4; it++) {
            int idx = it * 128 + tid;
            int r = idx >> 3, c8 = (idx & 7) * 8;
            CP_ASYNC16(dst + (r * SP + c8) * 2, src + (size_t)r * DD + c8);
        }
    };
    auto stage_load = [&](int kt, int s) {
        uint32_t sb = sm + 2 * ATILE_BY + s * ASTAGE_BY;
        const size_t rb = hbase + (size_t)(kt * 64) * DD;
        tile_load(sb,                 Kh + rb);
        tile_load(sb + ATILE_BY,      Kl + rb);
        tile_load(sb + 2 * ATILE_BY,  Vh + rb);
        tile_load(sb + 3 * ATILE_BY,  Vl + rb);
    };

    {
        const size_t rb = hbase + (size_t)(qb * 64) * DD;
        tile_load(uQh, Qh + rb);
        tile_load(uQl, Ql + rb);
    }
    stage_load(0, 0);
    CP_COMMIT();
    CP_WAIT(0);
    __syncthreads();

    // persistent Q fragments (verified A-frag recipe)
    uint32_t aQh[4][4], aQl[4][4];
    {
        int ar = lane & 15, ac = (lane >> 4) * 8;
#pragma unroll
        for (int k = 0; k < 4; k++) {
            uint32_t ad = uQh + ((w * 16 + ar) * SP + k * 16 + ac) * 2;
            LDSM_X4(aQh[k][0], aQh[k][1], aQh[k][2], aQh[k][3], ad);
            LDSM_X4(aQl[k][0], aQl[k][1], aQl[k][2], aQl[k][3], ad + ATILE_BY);
        }
    }

    float o[8][4];
#pragma unroll
    for (int n = 0; n < 8; n++)
#pragma unroll
        for (int j = 0; j < 4; j++) o[n][j] = 0.f;
    float m0 = -1e30f, m1 = -1e30f, l0 = 0.f, l1 = 0.f;
    int row0 = qb * 64 + w * 16 + gid, row1 = row0 + 8;

    for (int kt = 0; kt <= qb; kt++) {
        if (kt < qb) { stage_load(kt + 1, (kt + 1) & 1); CP_COMMIT(); CP_WAIT(1); }
        else         { CP_WAIT(0); }
        __syncthreads();

        uint32_t sb  = sm + 2 * ATILE_BY + (kt & 1) * ASTAGE_BY;
        uint32_t uKh = sb, uKl = sb + ATILE_BY;
        uint32_t uVh = sb + 2 * ATILE_BY, uVl = sb + 3 * ATILE_BY;

        // ---- scores S = (Qh+Ql)(Kh+Kl)^T (3 terms), fp32 accum
        float c[8][4];
#pragma unroll
        for (int n = 0; n < 8; n++)
#pragma unroll
            for (int j = 0; j < 4; j++) c[n][j] = 0.f;
        {
            int br = lane & 7, bc = ((lane >> 3) & 1) * 8;
            uint32_t bH[2], bL[2];
#pragma unroll
            for (int k = 0; k < 4; k++)
#pragma unroll
                for (int n = 0; n < 8; n++) {
                    uint32_t kd = ((n * 8 + br) * SP + k * 16 + bc) * 2;
                    LDSM_X2(bH[0], bH[1], uKh + kd);
                    LDSM_X2(bL[0], bL[1], uKl + kd);
                    MMA16816(c[n], aQh[k], bH);
                    MMA16816(c[n], aQh[k], bL);
                    MMA16816(c[n], aQl[k], bH);
                }
        }

        // ---- scale + causal mask (diag tile only)
#pragma unroll
        for (int n = 0; n < 8; n++)
#pragma unroll
            for (int j = 0; j < 4; j++) c[n][j] *= 0.125f;
        if (kt == qb) {
#pragma unroll
            for (int n = 0; n < 8; n++) {
                int col = kt * 64 + n * 8 + tig * 2;
                if (col     > row0) c[n][0] = -1e30f;
                if (col + 1 > row0) c[n][1] = -1e30f;
                if (col     > row1) c[n][2] = -1e30f;
                if (col + 1 > row1) c[n][3] = -1e30f;
            }
        }

        // ---- online softmax (rows gid / gid+8; quad = lanes sharing gid)
        float t0 = -1e30f, t1 = -1e30f;
#pragma unroll
        for (int n = 0; n < 8; n++) {
            t0 = fmaxf(t0, fmaxf(c[n][0], c[n][1]));
            t1 = fmaxf(t1, fmaxf(c[n][2], c[n][3]));
        }
        t0 = fmaxf(t0, __shfl_xor_sync(0xffffffffu, t0, 1));
        t0 = fmaxf(t0, __shfl_xor_sync(0xffffffffu, t0, 2));
        t1 = fmaxf(t1, __shfl_xor_sync(0xffffffffu, t1, 1));
        t1 = fmaxf(t1, __shfl_xor_sync(0xffffffffu, t1, 2));
        float m0n = fmaxf(m0, t0), m1n = fmaxf(m1, t1);
        float a0 = __expf(m0 - m0n), a1 = __expf(m1 - m1n);
        l0 *= a0; l1 *= a1;
#pragma unroll
        for (int n = 0; n < 8; n++) {
            o[n][0] *= a0; o[n][1] *= a0; o[n][2] *= a1; o[n][3] *= a1;
        }
#pragma unroll
        for (int n = 0; n < 8; n++) {
            c[n][0] = __expf(c[n][0] - m0n); c[n][1] = __expf(c[n][1] - m0n);
            c[n][2] = __expf(c[n][2] - m1n); c[n][3] = __expf(c[n][3] - m1n);
            l0 += c[n][0] + c[n][1];
            l1 += c[n][2] + c[n][3];
        }
        m0 = m0n; m1 = m1n;

        // ---- PV: O += (Ph+Pl)(Vh+Vl) (3 terms). P packed C->A in regs.
        {
            uint32_t bH[2], bL[2];
            int vr = lane & 15;
#pragma unroll
            for (int kk = 0; kk < 4; kk++) {
                uint32_t aPh[4], aPl[4];
                aPh[0] = pack2(c[2*kk][0],     c[2*kk][1]);
                aPh[1] = pack2(c[2*kk][2],     c[2*kk][3]);
                aPh[2] = pack2(c[2*kk+1][0],   c[2*kk+1][1]);
                aPh[3] = pack2(c[2*kk+1][2],   c[2*kk+1][3]);
                aPl[0] = packlo(c[2*kk][0],    c[2*kk][1],   aPh[0]);
                aPl[1] = packlo(c[2*kk][2],    c[2*kk][3],   aPh[1]);
                aPl[2] = packlo(c[2*kk+1][0],  c[2*kk+1][1], aPh[2]);
                aPl[3] = packlo(c[2*kk+1][2],  c[2*kk+1][3], aPh[3]);
#pragma unroll
                for (int nd = 0; nd < 8; nd++) {
                    uint32_t vd = ((kk * 16 + vr) * SP + nd * 8) * 2;
                    LDSM_X2_T(bH[0], bH[1], uVh + vd);
                    LDSM_X2_T(bL[0], bL[1], uVl + vd);
                    MMA16816(o[nd], aPh, bH);
                    MMA16816(o[nd], aPh, bL);
                    MMA16816(o[nd], aPl, bH);
                }
            }
        }
        __syncthreads();
    }

    // ---- finalize: reduce l over quad, normalize, emit bf16 hi/lo
    l0 += __shfl_xor_sync(0xffffffffu, l0, 1);
    l0 += __shfl_xor_sync(0xffffffffu, l0, 2);
    l1 += __shfl_xor_sync(0xffffffffu, l1, 1);
    l1 += __shfl_xor_sync(0xffffffffu, l1, 2);
    float i0 = 1.f / l0, i1 = 1.f / l1;
#pragma unroll
    for (int nd = 0; nd < 8; nd++) {
        int col = nd * 8 + tig * 2;
        float y0 = o[nd][0] * i0, y1 = o[nd][1] * i0;
        float z0 = o[nd][2] * i1, z1 = o[nd][3] * i1;
        uint32_t hp0 = pack2(y0, y1), hp1 = pack2(z0, z1);
        size_t off0 = hbase + (size_t)row0 * DD + col;
        size_t off1 = hbase + (size_t)row1 * DD + col;
        *(uint32_t*)&Yh[off0] = hp0;
        *(uint32_t*)&Yh[off1] = hp1;
        *(uint32_t*)&Yl[off0] = packlo(y0, y1, hp0);
        *(uint32_t*)&Yl[off1] = packlo(z0, z1, hp1);
    }
}

// ---------------------------------------------------------------------------
// Launch: splits -> fused QKV GEMM -> mma attention -> output GEMM.
// All graph-capturable, no allocs.
// ---------------------------------------------------------------------------
extern "C" void kernel_launch(void* const* d_in, const int* in_sizes, int n_in,
                              void* d_out, int out_size)
{
    const float* x  = (const float*)d_in[0];
    const float* Wq = (const float*)d_in[1];
    const float* bq = (const float*)d_in[2];
    const float* Wk = (const float*)d_in[3];
    const float* bk = (const float*)d_in[4];
    const float* Wv = (const float*)d_in[5];
    const float* bv = (const float*)d_in[6];
    const float* Wp = (const float*)d_in[7];
    const float* bp = (const float*)d_in[8];
    float* out = (float*)d_out;

    __nv_bfloat16 *xh, *xl, *wh, *wl, *qh, *ql, *kh, *kl, *vh, *vl, *yh, *yl;
    cudaGetSymbolAddress((void**)&xh, g_xh);
    cudaGetSymbolAddress((void**)&xl, g_xl);
    cudaGetSymbolAddress((void**)&wh, g_wh);
    cudaGetSymbolAddress((void**)&wl, g_wl);
    cudaGetSymbolAddress((void**)&qh, g_qh);
    cudaGetSymbolAddress((void**)&ql, g_ql);
    cudaGetSymbolAddress((void**)&kh, g_kh);
    cudaGetSymbolAddress((void**)&kl, g_kl);
    cudaGetSymbolAddress((void**)&vh, g_vh);
    cudaGetSymbolAddress((void**)&vl, g_vl);
    cudaGetSymbolAddress((void**)&yh, g_yh);
    cudaGetSymbolAddress((void**)&yl, g_yl);

    cudaFuncSetAttribute(gemm_qkv, cudaFuncAttributeMaxDynamicSharedMemorySize, GT_SMEM);
    cudaFuncSetAttribute(gemm_out, cudaFuncAttributeMaxDynamicSharedMemorySize, GT_SMEM);
    cudaFuncSetAttribute(attn_mma, cudaFuncAttributeMaxDynamicSharedMemorySize, ATT_SMEM);

    const int NX4 = BT * DD / 4;
    const int NW4 = DD * DD / 4;

    split_bf16<<<NX4 / 256, 256>>>(x, xh, xl, NX4);
    split_bf16<<<NW4 / 256, 256>>>(Wq, wh + 0 * DD * DD, wl + 0 * DD * DD, NW4);
    split_bf16<<<NW4 / 256, 256>>>(Wk, wh + 1 * DD * DD, wl + 1 * DD * DD, NW4);
    split_bf16<<<NW4 / 256, 256>>>(Wv, wh + 2 * DD * DD, wl + 2 * DD * DD, NW4);
    split_bf16<<<NW4 / 256, 256>>>(Wp, wh + 3 * DD * DD, wl + 3 * DD * DD, NW4);

    dim3 gq(24, BT / 128);   // fused Q|K|V: 768 CTAs
    gemm_qkv<<<gq, 256, GT_SMEM>>>(xh, xl, wh, wl, bq, bk, bv,
                                   qh, ql, kh, kl, vh, vl);

    dim3 ga(TT / 64, BB * HH);     // (32, 32)
    attn_mma<<<ga, 128, ATT_SMEM>>>(qh, ql, kh, kl, vh, vl, yh, yl);

    dim3 gg(DD / 128, BT / 128);   // (8, 32)
    gemm_out<<<gg, 256, GT_SMEM>>>(yh, yl, wh + 3 * DD * DD, wl + 3 * DD * DD, bp,
                                   out);
}